// round 1
// baseline (speedup 1.0000x reference)
#include <cuda_runtime.h>
#include <math.h>

#define NN 100000
#define NE 3200000
#define NG 128
#define H  128

// ---------------- scratch (device globals; no allocation allowed) ----------------
__device__ int   g_row[NE];
__device__ int   g_col[NE];
__device__ int   g_batch[NN];
__device__ int   g_deg[NN];
__device__ float g_dinv[NN];
__device__ float g_h  [(size_t)NN * H];
__device__ float g_m  [(size_t)NN * H];
__device__ float g_acc[(size_t)NN * H];
__device__ float g_pool[NG * H];
__device__ int   g_cnt[NG];

// Deterministic dtype probe: if the first 4 values, read as int64, are valid node
// ids, the buffer is int64; int32 data read as int64 packs two random ids and is
// astronomically unlikely to pass (needs 4 consecutive high words == 0).
__device__ __forceinline__ bool idx_is64(const void* p) {
    const long long* q = (const long long*)p;
    bool ok = true;
#pragma unroll
    for (int i = 0; i < 4; i++) {
        long long v = q[i];
        if (v < 0 || v >= NN) ok = false;
    }
    return ok;
}

// ---------------- kernels ----------------
__global__ void k_init() {
    int i = blockIdx.x * blockDim.x + threadIdx.x;
    if (i < NN) g_deg[i] = 1;            // self-loop
    if (i < NG) g_cnt[i] = 0;
    if (i < NG * H) g_pool[i] = 0.f;
}

__global__ void k_conv_edges(const void* ei) {
    bool is64 = idx_is64(ei);
    int stride = gridDim.x * blockDim.x;
    for (int e = blockIdx.x * blockDim.x + threadIdx.x; e < NE; e += stride) {
        int r, c;
        if (is64) {
            const long long* p = (const long long*)ei;
            r = (int)p[e]; c = (int)p[NE + e];
        } else {
            const int* p = (const int*)ei;
            r = p[e]; c = p[NE + e];
        }
        g_row[e] = r; g_col[e] = c;
        atomicAdd(&g_deg[c], 1);
    }
}

__global__ void k_conv_batch(const void* b, const void* ei) {
    bool is64 = idx_is64(ei);   // batch shares the platform int dtype with edge_index
    int stride = gridDim.x * blockDim.x;
    for (int n = blockIdx.x * blockDim.x + threadIdx.x; n < NN; n += stride) {
        int g = is64 ? (int)((const long long*)b)[n] : ((const int*)b)[n];
        g_batch[n] = g;
        atomicAdd(&g_cnt[g], 1);
    }
}

__global__ void k_dinv() {
    int n = blockIdx.x * blockDim.x + threadIdx.x;
    if (n < NN) g_dinv[n] = rsqrtf((float)g_deg[n]);
}

__global__ void k_embed(const float* __restrict__ x,
                        const float* __restrict__ W, const float* __restrict__ b) {
    int i = blockIdx.x * blockDim.x + threadIdx.x;   // NN*H threads exactly
    int node = i >> 7, j = i & 127;
    g_h[i] = fmaf(x[node], W[j], b[j]);
}

// h[NN,128] @ W[128,128]; epilogue scales by dinv[row] and writes m and acc(=m,
// which is the self-loop contribution). 256 thr, 8 warps, 4 rows/warp = 32 rows/blk.
__global__ void k_gemm(const float* __restrict__ Wl) {
    extern __shared__ float smem[];
    float* Ws = smem;            // 16384 floats
    float* hs = smem + 16384;    // 8*128 floats
    int t = threadIdx.x;
    {
        float4* d = (float4*)Ws;
        const float4* s = (const float4*)Wl;
        for (int i = t; i < 16384 / 4; i += 256) d[i] = s[i];
    }
    __syncthreads();
    int w = t >> 5, lane = t & 31;
    const float4* Ws4 = (const float4*)Ws;
#pragma unroll
    for (int rr = 0; rr < 4; rr++) {
        int row = blockIdx.x * 32 + w * 4 + rr;      // NN = 3125*32 exactly
        float4 hv = ((const float4*)(g_h + (size_t)row * H))[lane];
        ((float4*)(hs + w * 128))[lane] = hv;
        __syncwarp();
        float a0 = 0.f, a1 = 0.f, a2 = 0.f, a3 = 0.f;
#pragma unroll 4
        for (int k = 0; k < 128; k++) {
            float hk = hs[w * 128 + k];
            float4 wv = Ws4[k * 32 + lane];
            a0 = fmaf(hk, wv.x, a0); a1 = fmaf(hk, wv.y, a1);
            a2 = fmaf(hk, wv.z, a2); a3 = fmaf(hk, wv.w, a3);
        }
        float d = g_dinv[row];
        float4 o = make_float4(a0 * d, a1 * d, a2 * d, a3 * d);
        ((float4*)(g_m   + (size_t)row * H))[lane] = o;
        ((float4*)(g_acc + (size_t)row * H))[lane] = o;
        __syncwarp();
    }
}

// one warp per edge: gather 512B of m[row], vector-RED into acc[col]
__global__ void k_edge() {
    unsigned e = (blockIdx.x * blockDim.x + threadIdx.x) >> 5;
    if (e >= NE) return;
    int row = g_row[e], col = g_col[e];
    int lane = threadIdx.x & 31;
    float4 v = __ldg((const float4*)(g_m + (size_t)row * H) + lane);
    float* dst = g_acc + (size_t)col * H + lane * 4;
    asm volatile("red.global.add.v4.f32 [%0], {%1,%2,%3,%4};"
                 :: "l"(dst), "f"(v.x), "f"(v.y), "f"(v.z), "f"(v.w) : "memory");
}

__global__ void k_relu(const float* __restrict__ bias) {
    int i = blockIdx.x * blockDim.x + threadIdx.x;   // NN*32 float4s exactly
    int node = i >> 5, j4 = i & 31;
    float d = g_dinv[node];
    float4 a = ((const float4*)g_acc)[i];
    float4 b = ((const float4*)bias)[j4];
    float4 o;
    o.x = fmaxf(fmaf(d, a.x, b.x), 0.f);
    o.y = fmaxf(fmaf(d, a.y, b.y), 0.f);
    o.z = fmaxf(fmaf(d, a.z, b.z), 0.f);
    o.w = fmaxf(fmaf(d, a.w, b.w), 0.f);
    ((float4*)g_h)[i] = o;
}

__global__ void k_pool() {
    unsigned n = (blockIdx.x * blockDim.x + threadIdx.x) >> 5;
    if (n >= NN) return;
    int lane = threadIdx.x & 31;
    float4 v = ((const float4*)(g_h + (size_t)n * H))[lane];
    int g = g_batch[n];
    float* dst = g_pool + g * H + lane * 4;
    asm volatile("red.global.add.v4.f32 [%0], {%1,%2,%3,%4};"
                 :: "l"(dst), "f"(v.x), "f"(v.y), "f"(v.z), "f"(v.w) : "memory");
}

__global__ void k_classifier(const float* __restrict__ Wc1, const float* __restrict__ bc1,
                             const float* __restrict__ Wc2, const float* __restrict__ bc2,
                             float* __restrict__ out) {
    __shared__ float gs[128];
    __shared__ float zs[64];
    int b = blockIdx.x, t = threadIdx.x;
    float cnt = fmaxf((float)g_cnt[b], 1.f);
    gs[t] = g_pool[b * H + t] / cnt;
    __syncthreads();
    if (t < 64) {
        float z = bc1[t];
#pragma unroll 4
        for (int k = 0; k < 128; k++) z = fmaf(gs[k], Wc1[k * 64 + t], z);
        z = fmaxf(z, 0.f);
        zs[t] = z * Wc2[t];
    }
    __syncthreads();
    if (t == 0) {
        float s = bc2[0];
#pragma unroll
        for (int k = 0; k < 64; k++) s += zs[k];
        out[b] = 1.f / (1.f + expf(-s));
    }
}

// ---------------- launch ----------------
extern "C" void kernel_launch(void* const* d_in, const int* in_sizes, int n_in,
                              void* d_out, int out_size) {
    const float* x     = (const float*)d_in[0];
    const void*  ei    = d_in[1];
    const void*  batch = d_in[2];
    const float* W_emb = (const float*)d_in[3];
    const float* b_emb = (const float*)d_in[4];
    const float* W_gnn = (const float*)d_in[5];
    const float* b_gnn = (const float*)d_in[6];
    const float* W_c1  = (const float*)d_in[7];
    const float* b_c1  = (const float*)d_in[8];
    const float* W_c2  = (const float*)d_in[9];
    const float* b_c2  = (const float*)d_in[10];
    float* out = (float*)d_out;

    cudaFuncSetAttribute(k_gemm, cudaFuncAttributeMaxDynamicSharedMemorySize, 70 * 1024);
    const int GEMM_SMEM = (16384 + 8 * 128) * 4;

    k_init<<<(NN + 255) / 256, 256>>>();
    k_conv_edges<<<12500, 256>>>(ei);
    k_conv_batch<<<(NN + 255) / 256, 256>>>(batch, ei);
    k_dinv<<<(NN + 255) / 256, 256>>>();
    k_embed<<<NN * H / 256, 256>>>(x, W_emb, b_emb);

    for (int l = 0; l < 3; l++) {
        k_gemm<<<NN / 32, 256, GEMM_SMEM>>>(W_gnn + (size_t)l * H * H);
        k_edge<<<(unsigned)((size_t)NE * 32 / 256), 256>>>();
        k_relu<<<NN * 32 / 256, 256>>>(b_gnn + l * H);
    }

    k_pool<<<NN * 32 / 256, 256>>>();
    k_classifier<<<NG, 128>>>(W_c1, b_c1, W_c2, b_c2, out);
}

// round 2
// speedup vs baseline: 2.7383x; 2.7383x over previous
#include <cuda_runtime.h>
#include <math.h>

#define NN 100000
#define NE 3200000
#define NG 128
#define H  128

// ---------------- scratch (device globals; no allocation allowed) ----------------
__device__ int   g_row[NE];
__device__ int   g_col[NE];
__device__ int   g_csr[NE];
__device__ int   g_off[NN + 1];
__device__ int   g_cur[NN];
__device__ int   g_deg[NN];
__device__ int   g_bsum[128];
__device__ int   g_batch[NN];
__device__ int   g_cnt[NG];
__device__ float g_dinv[NN];
__device__ float g_h[(size_t)NN * H];
__device__ float g_m[(size_t)NN * H];
__device__ float g_pool[NG * H];
__device__ float g_u[H];
__device__ float g_v[H];

// Deterministic dtype probe: 4 leading values read as int64 all being valid node
// ids implies int64 layout (int32 data read as int64 packs two random ids and is
// astronomically unlikely to stay < NN four times in a row).
__device__ __forceinline__ bool idx_is64(const void* p) {
    const long long* q = (const long long*)p;
    bool ok = true;
#pragma unroll
    for (int i = 0; i < 4; i++) {
        long long v = q[i];
        if (v < 0 || v >= NN) ok = false;
    }
    return ok;
}

// ---------------- preprocessing ----------------
__global__ void k_init() {
    int i = blockIdx.x * blockDim.x + threadIdx.x;
    if (i < NN) g_deg[i] = 0;
    if (i < NG) g_cnt[i] = 0;
    if (i < NG * H) g_pool[i] = 0.f;
}

__global__ void k_conv_edges(const void* ei) {
    bool is64 = idx_is64(ei);
    int e = blockIdx.x * blockDim.x + threadIdx.x;   // exactly NE threads
    if (e >= NE) return;
    int r, c;
    if (is64) {
        const long long* p = (const long long*)ei;
        r = (int)p[e]; c = (int)p[NE + e];
    } else {
        const int* p = (const int*)ei;
        r = p[e]; c = p[NE + e];
    }
    g_row[e] = r; g_col[e] = c;
    atomicAdd(&g_deg[c], 1);
}

__global__ void k_conv_batch(const void* b, const void* ei) {
    bool is64 = idx_is64(ei);   // batch shares the platform index dtype with edge_index
    int n = blockIdx.x * blockDim.x + threadIdx.x;
    if (n >= NN) return;
    int g = is64 ? (int)((const long long*)b)[n] : ((const int*)b)[n];
    g_batch[n] = g;
    atomicAdd(&g_cnt[g], 1);
}

// exclusive scan of g_deg -> g_off (3 kernels)
__global__ void k_scan1() {
    __shared__ int s[1024];
    int t = threadIdx.x, gid = blockIdx.x * 1024 + t;
    int v = (gid < NN) ? g_deg[gid] : 0;
    s[t] = v; __syncthreads();
    for (int d = 1; d < 1024; d <<= 1) {
        int x = (t >= d) ? s[t - d] : 0;
        __syncthreads();
        s[t] += x; __syncthreads();
    }
    if (gid < NN) g_off[gid] = s[t] - v;     // block-local exclusive
    if (t == 1023) g_bsum[blockIdx.x] = s[1023];
}

__global__ void k_scan2(int nblk) {
    int run = 0;
    for (int b = 0; b < nblk; b++) { int tmp = g_bsum[b]; g_bsum[b] = run; run += tmp; }
    g_off[NN] = NE;
}

__global__ void k_scan3() {
    int gid = blockIdx.x * 1024 + threadIdx.x;
    if (gid < NN) {
        int o = g_off[gid] + g_bsum[blockIdx.x];
        g_off[gid] = o;
        g_cur[gid] = o;
    }
}

__global__ void k_dinv() {
    int n = blockIdx.x * blockDim.x + threadIdx.x;
    if (n < NN) g_dinv[n] = rsqrtf((float)(1 + g_deg[n]));   // +1 self-loop
}

__global__ void k_scatter() {
    int e = blockIdx.x * blockDim.x + threadIdx.x;
    if (e >= NE) return;
    int pos = atomicAdd(&g_cur[g_col[e]], 1);
    g_csr[pos] = g_row[e];
}

// u = W_emb @ W0, v = b_emb @ W0  (rank-1 collapse of embed + layer-0 linear)
__global__ void k_uv(const float* __restrict__ We, const float* __restrict__ be,
                     const float* __restrict__ W0) {
    int j = threadIdx.x;
    float u = 0.f, v = 0.f;
#pragma unroll 4
    for (int k = 0; k < 128; k++) {
        float w = W0[k * 128 + j];
        u = fmaf(We[k], w, u);
        v = fmaf(be[k], w, v);
    }
    g_u[j] = u; g_v[j] = v;
}

// m0[n] = dinv[n] * (x[n]*u + v)  — replaces embed + layer-0 GEMM
__global__ void k_m0(const float* __restrict__ x) {
    int i = blockIdx.x * blockDim.x + threadIdx.x;   // NN*32 float4 threads exactly
    int n = i >> 5, j4 = i & 31;
    float xv = __ldg(&x[n]);
    float d = g_dinv[n];
    float4 u = ((const float4*)g_u)[j4];
    float4 v = ((const float4*)g_v)[j4];
    float4 o;
    o.x = d * fmaf(xv, u.x, v.x);
    o.y = d * fmaf(xv, u.y, v.y);
    o.z = d * fmaf(xv, u.z, v.z);
    o.w = d * fmaf(xv, u.w, v.w);
    ((float4*)g_m)[i] = o;
}

// ---------------- per-layer GEMM: m = dinv ⊙ (h @ W) ----------------
// 256 thr / 8 warps, 4 rows per warp, W resident in smem.
__global__ void k_gemm(const float* __restrict__ Wl) {
    extern __shared__ float smem[];
    float* Ws = smem;                                 // 16384 floats
    float* hs = smem + 16384 + (threadIdx.x >> 5) * 512;
    int t = threadIdx.x;
    {
        float4* d = (float4*)Ws;
        const float4* s = (const float4*)Wl;
        for (int i = t; i < 4096; i += 256) d[i] = s[i];
    }
    __syncthreads();
    int w = t >> 5, lane = t & 31;
    int row0 = blockIdx.x * 32 + w * 4;               // NN = 3125 * 32 exactly
#pragma unroll
    for (int rr = 0; rr < 4; rr++)
        ((float4*)(hs + rr * 128))[lane] = ((const float4*)(g_h + (size_t)(row0 + rr) * H))[lane];
    __syncwarp();
    float4 acc[4];
#pragma unroll
    for (int rr = 0; rr < 4; rr++) acc[rr] = make_float4(0.f, 0.f, 0.f, 0.f);
    const float4* Ws4 = (const float4*)Ws;
#pragma unroll 4
    for (int k = 0; k < 128; k++) {
        float4 wv = Ws4[k * 32 + lane];
#pragma unroll
        for (int rr = 0; rr < 4; rr++) {
            float hk = hs[rr * 128 + k];
            acc[rr].x = fmaf(hk, wv.x, acc[rr].x);
            acc[rr].y = fmaf(hk, wv.y, acc[rr].y);
            acc[rr].z = fmaf(hk, wv.z, acc[rr].z);
            acc[rr].w = fmaf(hk, wv.w, acc[rr].w);
        }
    }
#pragma unroll
    for (int rr = 0; rr < 4; rr++) {
        float d = g_dinv[row0 + rr];
        float4 o = make_float4(acc[rr].x * d, acc[rr].y * d, acc[rr].z * d, acc[rr].w * d);
        ((float4*)(g_m + (size_t)(row0 + rr) * H))[lane] = o;
    }
}

// ---------------- aggregation: warp per node, CSR neighbor sum, fused epilogue --
__global__ void k_agg(const float* __restrict__ bias, int last) {
    unsigned n = (blockIdx.x * blockDim.x + threadIdx.x) >> 5;
    if (n >= NN) return;
    int lane = threadIdx.x & 31;
    const float4* m4 = (const float4*)g_m;
    float4 a0 = m4[(size_t)n * 32 + lane];            // self-loop term
    float4 a1 = make_float4(0.f, 0.f, 0.f, 0.f);
    float4 a2 = make_float4(0.f, 0.f, 0.f, 0.f);
    float4 a3 = make_float4(0.f, 0.f, 0.f, 0.f);
    int s = g_off[n], e = g_off[n + 1];
    int i = s;
    for (; i + 4 <= e; i += 4) {
        int r0 = __ldg(g_csr + i), r1 = __ldg(g_csr + i + 1);
        int r2 = __ldg(g_csr + i + 2), r3 = __ldg(g_csr + i + 3);
        float4 v0 = __ldg(m4 + (size_t)r0 * 32 + lane);
        float4 v1 = __ldg(m4 + (size_t)r1 * 32 + lane);
        float4 v2 = __ldg(m4 + (size_t)r2 * 32 + lane);
        float4 v3 = __ldg(m4 + (size_t)r3 * 32 + lane);
        a0.x += v0.x; a0.y += v0.y; a0.z += v0.z; a0.w += v0.w;
        a1.x += v1.x; a1.y += v1.y; a1.z += v1.z; a1.w += v1.w;
        a2.x += v2.x; a2.y += v2.y; a2.z += v2.z; a2.w += v2.w;
        a3.x += v3.x; a3.y += v3.y; a3.z += v3.z; a3.w += v3.w;
    }
    for (; i < e; i++) {
        int r = __ldg(g_csr + i);
        float4 v = __ldg(m4 + (size_t)r * 32 + lane);
        a0.x += v.x; a0.y += v.y; a0.z += v.z; a0.w += v.w;
    }
    float sx = (a0.x + a1.x) + (a2.x + a3.x);
    float sy = (a0.y + a1.y) + (a2.y + a3.y);
    float sz = (a0.z + a1.z) + (a2.z + a3.z);
    float sw = (a0.w + a1.w) + (a2.w + a3.w);
    float d = g_dinv[n];
    float4 b = __ldg(((const float4*)bias) + lane);
    float4 o;
    o.x = fmaxf(fmaf(d, sx, b.x), 0.f);
    o.y = fmaxf(fmaf(d, sy, b.y), 0.f);
    o.z = fmaxf(fmaf(d, sz, b.z), 0.f);
    o.w = fmaxf(fmaf(d, sw, b.w), 0.f);
    if (!last) {
        ((float4*)g_h)[(size_t)n * 32 + lane] = o;
    } else {
        float* dst = g_pool + g_batch[n] * H + lane * 4;
        asm volatile("red.global.add.v4.f32 [%0], {%1,%2,%3,%4};"
                     :: "l"(dst), "f"(o.x), "f"(o.y), "f"(o.z), "f"(o.w) : "memory");
    }
}

// ---------------- classifier ----------------
__global__ void k_classifier(const float* __restrict__ Wc1, const float* __restrict__ bc1,
                             const float* __restrict__ Wc2, const float* __restrict__ bc2,
                             float* __restrict__ out) {
    __shared__ float gs[128];
    __shared__ float zs[64];
    int b = blockIdx.x, t = threadIdx.x;
    float cnt = fmaxf((float)g_cnt[b], 1.f);
    gs[t] = g_pool[b * H + t] / cnt;
    __syncthreads();
    if (t < 64) {
        float z = bc1[t];
#pragma unroll 4
        for (int k = 0; k < 128; k++) z = fmaf(gs[k], Wc1[k * 64 + t], z);
        z = fmaxf(z, 0.f);
        zs[t] = z * Wc2[t];
    }
    __syncthreads();
    if (t == 0) {
        float s = bc2[0];
#pragma unroll
        for (int k = 0; k < 64; k++) s += zs[k];
        out[b] = 1.f / (1.f + expf(-s));
    }
}

// ---------------- launch ----------------
extern "C" void kernel_launch(void* const* d_in, const int* in_sizes, int n_in,
                              void* d_out, int out_size) {
    const float* x     = (const float*)d_in[0];
    const void*  ei    = d_in[1];
    const void*  batch = d_in[2];
    const float* W_emb = (const float*)d_in[3];
    const float* b_emb = (const float*)d_in[4];
    const float* W_gnn = (const float*)d_in[5];
    const float* b_gnn = (const float*)d_in[6];
    const float* W_c1  = (const float*)d_in[7];
    const float* b_c1  = (const float*)d_in[8];
    const float* W_c2  = (const float*)d_in[9];
    const float* b_c2  = (const float*)d_in[10];
    float* out = (float*)d_out;

    cudaFuncSetAttribute(k_gemm, cudaFuncAttributeMaxDynamicSharedMemorySize, 96 * 1024);
    const int GEMM_SMEM = (16384 + 8 * 512) * 4;     // 80 KB
    const int NSCAN = (NN + 1023) / 1024;            // 98

    k_init<<<(NN + 255) / 256, 256>>>();
    k_conv_edges<<<NE / 256, 256>>>(ei);
    k_conv_batch<<<(NN + 255) / 256, 256>>>(batch, ei);
    k_scan1<<<NSCAN, 1024>>>();
    k_scan2<<<1, 1>>>(NSCAN);
    k_scan3<<<NSCAN, 1024>>>();
    k_dinv<<<(NN + 255) / 256, 256>>>();
    k_scatter<<<NE / 256, 256>>>();
    k_uv<<<1, 128>>>(W_emb, b_emb, W_gnn);

    // layer 0 (GEMM collapsed into rank-1 update)
    k_m0<<<NN * 32 / 256, 256>>>(x);
    k_agg<<<NN * 32 / 256, 256>>>(b_gnn, 0);

    // layers 1..2
    for (int l = 1; l < 3; l++) {
        k_gemm<<<NN / 32, 256, GEMM_SMEM>>>(W_gnn + (size_t)l * H * H);
        k_agg<<<NN * 32 / 256, 256>>>(b_gnn + l * H, l == 2);
    }

    k_classifier<<<NG, 128>>>(W_c1, b_c1, W_c2, b_c2, out);
}

// round 3
// speedup vs baseline: 3.1586x; 1.1535x over previous
#include <cuda_runtime.h>
#include <cuda_bf16.h>
#include <math.h>

#define NN 100000
#define NN_PAD 100096            // 782 * 128
#define NE 3200000
#define NG 128
#define H  128

// ---------------- scratch (device globals; zero-initialized, no allocation) -----
__device__ int   g_row[NE];
__device__ int   g_col[NE];
__device__ int   g_csr[NE];
__device__ int   g_off[NN + 1];
__device__ int   g_cur[NN];
__device__ int   g_deg[NN];
__device__ int   g_bsum[128];
__device__ int   g_batch[NN];
__device__ int   g_cnt[NG];
__device__ float g_dinv[NN_PAD];                    // pad rows stay 0
__device__ float g_h[(size_t)NN_PAD * H];           // pad rows stay 0 (never written)
__device__ uint2 g_mb[(size_t)NN_PAD * 32];         // m as bf16: 128 bf16 = 32 uint2/row
__device__ float g_pool[NG * H];
__device__ float g_u[H];
__device__ float g_v[H];

// Deterministic dtype probe: 4 leading values read as int64 all being valid node
// ids implies int64 layout.
__device__ __forceinline__ bool idx_is64(const void* p) {
    const long long* q = (const long long*)p;
    bool ok = true;
#pragma unroll
    for (int i = 0; i < 4; i++) {
        long long v = q[i];
        if (v < 0 || v >= NN) ok = false;
    }
    return ok;
}

__device__ __forceinline__ unsigned f2tf32(float f) {
    unsigned r;
    asm("cvt.rna.tf32.f32 %0, %1;" : "=r"(r) : "f"(f));
    return r;
}

// ---------------- preprocessing ----------------
__global__ void k_init() {
    int i = blockIdx.x * blockDim.x + threadIdx.x;
    if (i < NN) g_deg[i] = 0;
    if (i < NG) g_cnt[i] = 0;
    if (i < NG * H) g_pool[i] = 0.f;
}

__global__ void k_conv_edges(const void* ei) {
    bool is64 = idx_is64(ei);
    int e = blockIdx.x * blockDim.x + threadIdx.x;
    if (e >= NE) return;
    int r, c;
    if (is64) {
        const long long* p = (const long long*)ei;
        r = (int)p[e]; c = (int)p[NE + e];
    } else {
        const int* p = (const int*)ei;
        r = p[e]; c = p[NE + e];
    }
    g_row[e] = r; g_col[e] = c;
    atomicAdd(&g_deg[c], 1);
}

__global__ void k_conv_batch(const void* b, const void* ei) {
    bool is64 = idx_is64(ei);
    int n = blockIdx.x * blockDim.x + threadIdx.x;
    if (n >= NN) return;
    int g = is64 ? (int)((const long long*)b)[n] : ((const int*)b)[n];
    g_batch[n] = g;
    atomicAdd(&g_cnt[g], 1);
}

__global__ void k_scan1() {
    __shared__ int s[1024];
    int t = threadIdx.x, gid = blockIdx.x * 1024 + t;
    int v = (gid < NN) ? g_deg[gid] : 0;
    s[t] = v; __syncthreads();
    for (int d = 1; d < 1024; d <<= 1) {
        int x = (t >= d) ? s[t - d] : 0;
        __syncthreads();
        s[t] += x; __syncthreads();
    }
    if (gid < NN) g_off[gid] = s[t] - v;
    if (t == 1023) g_bsum[blockIdx.x] = s[1023];
}

__global__ void k_scan2(int nblk) {
    int run = 0;
    for (int b = 0; b < nblk; b++) { int tmp = g_bsum[b]; g_bsum[b] = run; run += tmp; }
    g_off[NN] = NE;
}

__global__ void k_scan3() {   // + dinv fused
    int gid = blockIdx.x * 1024 + threadIdx.x;
    if (gid < NN) {
        int o = g_off[gid] + g_bsum[blockIdx.x];
        g_off[gid] = o;
        g_cur[gid] = o;
        g_dinv[gid] = rsqrtf((float)(1 + g_deg[gid]));
    }
}

__global__ void k_scatter() {
    int e = blockIdx.x * blockDim.x + threadIdx.x;
    if (e >= NE) return;
    int pos = atomicAdd(&g_cur[g_col[e]], 1);
    g_csr[pos] = g_row[e];
}

// u = W_emb @ W0, v = b_emb @ W0
__global__ void k_uv(const float* __restrict__ We, const float* __restrict__ be,
                     const float* __restrict__ W0) {
    int j = threadIdx.x;
    float u = 0.f, v = 0.f;
#pragma unroll 4
    for (int k = 0; k < 128; k++) {
        float w = W0[k * 128 + j];
        u = fmaf(We[k], w, u);
        v = fmaf(be[k], w, v);
    }
    g_u[j] = u; g_v[j] = v;
}

// m0[n] = dinv[n] * (x[n]*u + v), stored bf16
__global__ void k_m0(const float* __restrict__ x) {
    int i = blockIdx.x * blockDim.x + threadIdx.x;   // NN*32 threads
    int n = i >> 5, j4 = i & 31;
    float xv = __ldg(&x[n]);
    float d = g_dinv[n];
    float4 u = ((const float4*)g_u)[j4];
    float4 v = ((const float4*)g_v)[j4];
    __nv_bfloat162 p0 = __floats2bfloat162_rn(d * fmaf(xv, u.x, v.x), d * fmaf(xv, u.y, v.y));
    __nv_bfloat162 p1 = __floats2bfloat162_rn(d * fmaf(xv, u.z, v.z), d * fmaf(xv, u.w, v.w));
    uint2 o;
    o.x = *(unsigned*)&p0; o.y = *(unsigned*)&p1;
    g_mb[(size_t)n * 32 + j4] = o;
}

// ---------------- tf32 tensor-core GEMM: m = dinv ⊙ (h @ W), bf16 out ----------
// 256 thr / 8 warps; block computes 128 rows x 128 cols, K=128.
// smem: hs[128][132] (tf32 bits), Ws[128][136] (tf32 bits, [k][n]).
#define HS_STRIDE 132
#define WS_STRIDE 136
__global__ void __launch_bounds__(256) k_gemm(const float* __restrict__ Wl) {
    extern __shared__ float smem[];
    float* hs = smem;                       // 128*132
    float* Ws = smem + 128 * HS_STRIDE;     // 128*136
    int t = threadIdx.x;
    int row0 = blockIdx.x * 128;

    // stage h tile (tf32-converted)
    for (int idx = t; idx < 128 * 32; idx += 256) {
        int r = idx >> 5, c4 = idx & 31;
        float4 v = ((const float4*)(g_h + (size_t)(row0 + r) * H))[c4];
        float* d = hs + r * HS_STRIDE + c4 * 4;
        d[0] = __uint_as_float(f2tf32(v.x));
        d[1] = __uint_as_float(f2tf32(v.y));
        d[2] = __uint_as_float(f2tf32(v.z));
        d[3] = __uint_as_float(f2tf32(v.w));
    }
    // stage W (tf32-converted), layout [k][n]
    for (int idx = t; idx < 128 * 32; idx += 256) {
        int k = idx >> 5, c4 = idx & 31;
        float4 v = ((const float4*)(Wl + (size_t)k * H))[c4];
        float* d = Ws + k * WS_STRIDE + c4 * 4;
        d[0] = __uint_as_float(f2tf32(v.x));
        d[1] = __uint_as_float(f2tf32(v.y));
        d[2] = __uint_as_float(f2tf32(v.z));
        d[3] = __uint_as_float(f2tf32(v.w));
    }
    __syncthreads();

    int w = t >> 5, lane = t & 31;
    int g = lane >> 2, tt = lane & 3;
    int wr = w * 16;                        // warp's 16-row slice

    float c[16][4];
#pragma unroll
    for (int nt = 0; nt < 16; nt++)
        c[nt][0] = c[nt][1] = c[nt][2] = c[nt][3] = 0.f;

#pragma unroll
    for (int kk = 0; kk < 16; kk++) {
        int kb = kk * 8;
        unsigned a0 = __float_as_uint(hs[(wr + g) * HS_STRIDE + kb + tt]);
        unsigned a1 = __float_as_uint(hs[(wr + g + 8) * HS_STRIDE + kb + tt]);
        unsigned a2 = __float_as_uint(hs[(wr + g) * HS_STRIDE + kb + tt + 4]);
        unsigned a3 = __float_as_uint(hs[(wr + g + 8) * HS_STRIDE + kb + tt + 4]);
#pragma unroll
        for (int nt = 0; nt < 16; nt++) {
            unsigned b0 = __float_as_uint(Ws[(kb + tt) * WS_STRIDE + nt * 8 + g]);
            unsigned b1 = __float_as_uint(Ws[(kb + tt + 4) * WS_STRIDE + nt * 8 + g]);
            asm volatile(
                "mma.sync.aligned.m16n8k8.row.col.f32.tf32.tf32.f32 "
                "{%0,%1,%2,%3}, {%4,%5,%6,%7}, {%8,%9}, {%0,%1,%2,%3};"
                : "+f"(c[nt][0]), "+f"(c[nt][1]), "+f"(c[nt][2]), "+f"(c[nt][3])
                : "r"(a0), "r"(a1), "r"(a2), "r"(a3), "r"(b0), "r"(b1));
        }
    }

    // epilogue: scale by dinv, pack bf16 pairs
    int r0 = row0 + wr + g, r1 = r0 + 8;
    float d0 = g_dinv[r0], d1 = g_dinv[r1];
    __nv_bfloat162* mb = (__nv_bfloat162*)g_mb;
#pragma unroll
    for (int nt = 0; nt < 16; nt++) {
        int colp = nt * 4 + tt;            // (col = nt*8 + 2*tt) / 2
        __nv_bfloat162 p0 = __floats2bfloat162_rn(c[nt][0] * d0, c[nt][1] * d0);
        __nv_bfloat162 p1 = __floats2bfloat162_rn(c[nt][2] * d1, c[nt][3] * d1);
        mb[(size_t)r0 * 64 + colp] = p0;
        mb[(size_t)r1 * 64 + colp] = p1;
    }
}

// ---------------- aggregation: warp per node, bf16 gathers, fused epilogue -----
__device__ __forceinline__ void acc_u2(float4& a, uint2 u) {
    float2 f0 = __bfloat1622float2(*(__nv_bfloat162*)&u.x);
    float2 f1 = __bfloat1622float2(*(__nv_bfloat162*)&u.y);
    a.x += f0.x; a.y += f0.y; a.z += f1.x; a.w += f1.y;
}

__global__ void k_agg(const float* __restrict__ bias, int last) {
    unsigned n = (blockIdx.x * blockDim.x + threadIdx.x) >> 5;
    if (n >= NN) return;
    int lane = threadIdx.x & 31;
    const uint2* mb = g_mb;
    float4 a0 = make_float4(0.f, 0.f, 0.f, 0.f);
    float4 a1 = a0, a2 = a0, a3 = a0;
    acc_u2(a0, __ldg(mb + (size_t)n * 32 + lane));    // self-loop term
    int s = g_off[n], e = g_off[n + 1];
    int i = s;
    for (; i + 4 <= e; i += 4) {
        int r0 = __ldg(g_csr + i),     r1 = __ldg(g_csr + i + 1);
        int r2 = __ldg(g_csr + i + 2), r3 = __ldg(g_csr + i + 3);
        uint2 v0 = __ldg(mb + (size_t)r0 * 32 + lane);
        uint2 v1 = __ldg(mb + (size_t)r1 * 32 + lane);
        uint2 v2 = __ldg(mb + (size_t)r2 * 32 + lane);
        uint2 v3 = __ldg(mb + (size_t)r3 * 32 + lane);
        acc_u2(a0, v0); acc_u2(a1, v1); acc_u2(a2, v2); acc_u2(a3, v3);
    }
    for (; i < e; i++) {
        int r = __ldg(g_csr + i);
        acc_u2(a0, __ldg(mb + (size_t)r * 32 + lane));
    }
    float sx = (a0.x + a1.x) + (a2.x + a3.x);
    float sy = (a0.y + a1.y) + (a2.y + a3.y);
    float sz = (a0.z + a1.z) + (a2.z + a3.z);
    float sw = (a0.w + a1.w) + (a2.w + a3.w);
    float d = g_dinv[n];
    float4 b = __ldg(((const float4*)bias) + lane);
    float4 o;
    o.x = fmaxf(fmaf(d, sx, b.x), 0.f);
    o.y = fmaxf(fmaf(d, sy, b.y), 0.f);
    o.z = fmaxf(fmaf(d, sz, b.z), 0.f);
    o.w = fmaxf(fmaf(d, sw, b.w), 0.f);
    if (!last) {
        ((float4*)g_h)[(size_t)n * 32 + lane] = o;
    } else {
        float* dst = g_pool + g_batch[n] * H + lane * 4;
        asm volatile("red.global.add.v4.f32 [%0], {%1,%2,%3,%4};"
                     :: "l"(dst), "f"(o.x), "f"(o.y), "f"(o.z), "f"(o.w) : "memory");
    }
}

// ---------------- classifier ----------------
__global__ void k_classifier(const float* __restrict__ Wc1, const float* __restrict__ bc1,
                             const float* __restrict__ Wc2, const float* __restrict__ bc2,
                             float* __restrict__ out) {
    __shared__ float gs[128];
    __shared__ float zs[64];
    int b = blockIdx.x, t = threadIdx.x;
    float cnt = fmaxf((float)g_cnt[b], 1.f);
    gs[t] = g_pool[b * H + t] / cnt;
    __syncthreads();
    if (t < 64) {
        float z = bc1[t];
#pragma unroll 4
        for (int k = 0; k < 128; k++) z = fmaf(gs[k], Wc1[k * 64 + t], z);
        z = fmaxf(z, 0.f);
        zs[t] = z * Wc2[t];
    }
    __syncthreads();
    if (t == 0) {
        float s = bc2[0];
#pragma unroll
        for (int k = 0; k < 64; k++) s += zs[k];
        out[b] = 1.f / (1.f + expf(-s));
    }
}

// ---------------- launch ----------------
extern "C" void kernel_launch(void* const* d_in, const int* in_sizes, int n_in,
                              void* d_out, int out_size) {
    const float* x     = (const float*)d_in[0];
    const void*  ei    = d_in[1];
    const void*  batch = d_in[2];
    const float* W_emb = (const float*)d_in[3];
    const float* b_emb = (const float*)d_in[4];
    const float* W_gnn = (const float*)d_in[5];
    const float* b_gnn = (const float*)d_in[6];
    const float* W_c1  = (const float*)d_in[7];
    const float* b_c1  = (const float*)d_in[8];
    const float* W_c2  = (const float*)d_in[9];
    const float* b_c2  = (const float*)d_in[10];
    float* out = (float*)d_out;

    const int GEMM_SMEM = (128 * HS_STRIDE + 128 * WS_STRIDE) * 4;   // 137216 B
    cudaFuncSetAttribute(k_gemm, cudaFuncAttributeMaxDynamicSharedMemorySize, GEMM_SMEM);
    const int NSCAN = (NN + 1023) / 1024;

    k_init<<<(NN + 255) / 256, 256>>>();
    k_conv_edges<<<NE / 256, 256>>>(ei);
    k_conv_batch<<<(NN + 255) / 256, 256>>>(batch, ei);
    k_scan1<<<NSCAN, 1024>>>();
    k_scan2<<<1, 1>>>(NSCAN);
    k_scan3<<<NSCAN, 1024>>>();
    k_scatter<<<NE / 256, 256>>>();
    k_uv<<<1, 128>>>(W_emb, b_emb, W_gnn);

    // layer 0 (rank-1 collapse)
    k_m0<<<NN * 32 / 256, 256>>>(x);
    k_agg<<<NN * 32 / 256, 256>>>(b_gnn, 0);

    // layers 1..2
    for (int l = 1; l < 3; l++) {
        k_gemm<<<NN_PAD / 128, 256, GEMM_SMEM>>>(W_gnn + (size_t)l * H * H);
        k_agg<<<NN * 32 / 256, 256>>>(b_gnn + l * H, l == 2);
    }

    k_classifier<<<NG, 128>>>(W_c1, b_c1, W_c2, b_c2, out);
}

// round 4
// speedup vs baseline: 3.9604x; 1.2539x over previous
#include <cuda_runtime.h>
#include <cuda_bf16.h>
#include <math.h>

#define NN 100000
#define NN_PAD 100096            // 782 * 128
#define NE 3200000
#define NG 128
#define H  128

// ---------------- scratch (device globals; zero-initialized, no allocation) -----
__device__ int      g_row[NE];
__device__ int      g_col[NE];
__device__ int      g_csr[NE];
__device__ int      g_off[NN + 1];
__device__ int      g_cur[NN];
__device__ int      g_deg[NN];          // zero at entry (module-load / classifier tail)
__device__ int      g_bsum[128];
__device__ int      g_batch[NN];
__device__ int      g_cnt[NG];          // zero at entry
__device__ float    g_dinv[NN_PAD];     // pad rows stay 0
__device__ unsigned g_hb[(size_t)NN_PAD * 64];   // h in bf16 (64 uints = 128 bf16/row)
__device__ uint2    g_mb[(size_t)NN_PAD * 32];   // m in bf16 (32 uint2/row)
__device__ float    g_pool[NG * H];     // zero at entry
__device__ float    g_u[H];
__device__ float    g_v[H];

// Deterministic dtype probe: 4 leading values read as int64 all being valid node
// ids implies int64 layout.
__device__ __forceinline__ bool idx_is64(const void* p) {
    const long long* q = (const long long*)p;
    bool ok = true;
#pragma unroll
    for (int i = 0; i < 4; i++) {
        long long v = q[i];
        if (v < 0 || v >= NN) ok = false;
    }
    return ok;
}

// ---------------- preprocessing ----------------
__global__ void k_conv_edges(const void* ei) {
    bool is64 = idx_is64(ei);
    int e = blockIdx.x * blockDim.x + threadIdx.x;
    if (e >= NE) return;
    int r, c;
    if (is64) {
        const long long* p = (const long long*)ei;
        r = (int)p[e]; c = (int)p[NE + e];
    } else {
        const int* p = (const int*)ei;
        r = p[e]; c = p[NE + e];
    }
    g_row[e] = r; g_col[e] = c;
    atomicAdd(&g_deg[c], 1);
}

__global__ void k_conv_batch(const void* b, const void* ei) {
    bool is64 = idx_is64(ei);
    int n = blockIdx.x * blockDim.x + threadIdx.x;
    if (n >= NN) return;
    int g = is64 ? (int)((const long long*)b)[n] : ((const int*)b)[n];
    g_batch[n] = g;
    atomicAdd(&g_cnt[g], 1);
}

__global__ void k_scan1() {
    __shared__ int s[1024];
    int t = threadIdx.x, gid = blockIdx.x * 1024 + t;
    int v = (gid < NN) ? g_deg[gid] : 0;
    s[t] = v; __syncthreads();
    for (int d = 1; d < 1024; d <<= 1) {
        int x = (t >= d) ? s[t - d] : 0;
        __syncthreads();
        s[t] += x; __syncthreads();
    }
    if (gid < NN) g_off[gid] = s[t] - v;
    if (t == 1023) g_bsum[blockIdx.x] = s[1023];
}

// adds block-prefix (parallel sum of preceding bsums) + fused dinv
__global__ void k_scan3() {
    __shared__ int s[128];
    int t = threadIdx.x, nb = blockIdx.x;
    if (t < 128) s[t] = (t < nb) ? g_bsum[t] : 0;
    __syncthreads();
    for (int d = 64; d > 0; d >>= 1) {
        if (t < d) s[t] += s[t + d];
        __syncthreads();
    }
    int base = s[0];
    int gid = nb * 1024 + t;
    if (gid < NN) {
        int o = g_off[gid] + base;
        g_off[gid] = o;
        g_cur[gid] = o;
        g_dinv[gid] = rsqrtf((float)(1 + g_deg[gid]));
    }
    if (nb == 0 && t == 0) g_off[NN] = NE;
}

__global__ void k_scatter() {
    int e = blockIdx.x * blockDim.x + threadIdx.x;
    if (e >= NE) return;
    int pos = atomicAdd(&g_cur[g_col[e]], 1);
    g_csr[pos] = g_row[e];
}

// u = W_emb @ W0, v = b_emb @ W0
__global__ void k_uv(const float* __restrict__ We, const float* __restrict__ be,
                     const float* __restrict__ W0) {
    int j = threadIdx.x;
    float u = 0.f, v = 0.f;
#pragma unroll 4
    for (int k = 0; k < 128; k++) {
        float w = W0[k * 128 + j];
        u = fmaf(We[k], w, u);
        v = fmaf(be[k], w, v);
    }
    g_u[j] = u; g_v[j] = v;
}

// m0[n] = dinv[n] * (x[n]*u + v), stored bf16
__global__ void k_m0(const float* __restrict__ x) {
    int i = blockIdx.x * blockDim.x + threadIdx.x;   // NN*32 threads
    int n = i >> 5, j4 = i & 31;
    float xv = __ldg(&x[n]);
    float d = g_dinv[n];
    float4 u = ((const float4*)g_u)[j4];
    float4 v = ((const float4*)g_v)[j4];
    __nv_bfloat162 p0 = __floats2bfloat162_rn(d * fmaf(xv, u.x, v.x), d * fmaf(xv, u.y, v.y));
    __nv_bfloat162 p1 = __floats2bfloat162_rn(d * fmaf(xv, u.z, v.z), d * fmaf(xv, u.w, v.w));
    uint2 o;
    o.x = *(unsigned*)&p0; o.y = *(unsigned*)&p1;
    g_mb[(size_t)n * 32 + j4] = o;
}

// ---------------- bf16 tensor-core GEMM: m = dinv ⊙ (h @ W), bf16 out ----------
// 256 thr / 8 warps; block computes 128 rows x 128 cols, K=128, mma.m16n8k16.
// hs: bf16 pairs [row][kp], stride 68 uints (conflict-free LDS.32).
// WtP: B pairs uint2 [n][j], j=ks*4+tt holds kp (ks*8+tt, ks*8+tt+4),
//      rotated by 4*(n&3) for conflict-free LDS.64.
#define AST 68
__global__ void __launch_bounds__(256, 2) k_gemm(const float* __restrict__ Wl) {
    extern __shared__ unsigned smem_u[];
    unsigned* hs  = smem_u;                 // 128*68 uints
    uint2*    WtP = (uint2*)(smem_u + 128 * AST);   // 128*32 uint2
    int t = threadIdx.x;
    int row0 = blockIdx.x * 128;

    // stage h (already bf16 pairs): straight copy, 128 rows x 16 uint4
    {
        const uint4* src = (const uint4*)(g_hb + (size_t)row0 * 64);
        for (int idx = t; idx < 128 * 16; idx += 256) {
            int r = idx >> 4, c = idx & 15;
            *(uint4*)(hs + r * AST + c * 4) = src[r * 16 + c];
        }
    }
    // stage W: transpose + bf16-pack into paired layout
    for (int idx = t; idx < 32 * 128; idx += 256) {
        int j = idx >> 7, n = idx & 127;     // consecutive threads -> consecutive n
        int ks = j >> 2, tt = j & 3;
        int kp0 = ks * 8 + tt, kp1 = kp0 + 4;
        __nv_bfloat162 p0 = __floats2bfloat162_rn(Wl[(2 * kp0) * 128 + n],
                                                  Wl[(2 * kp0 + 1) * 128 + n]);
        __nv_bfloat162 p1 = __floats2bfloat162_rn(Wl[(2 * kp1) * 128 + n],
                                                  Wl[(2 * kp1 + 1) * 128 + n]);
        uint2 o; o.x = *(unsigned*)&p0; o.y = *(unsigned*)&p1;
        WtP[n * 32 + ((j + 4 * (n & 3)) & 31)] = o;
    }
    __syncthreads();

    int w = t >> 5, lane = t & 31, g = lane >> 2, tt = lane & 3;
    int wr = w * 16;

    float c[16][4];
#pragma unroll
    for (int nt = 0; nt < 16; nt++)
        c[nt][0] = c[nt][1] = c[nt][2] = c[nt][3] = 0.f;

#pragma unroll
    for (int ks = 0; ks < 8; ks++) {
        int kb = ks * 8;
        unsigned a0 = hs[(wr + g) * AST + kb + tt];
        unsigned a1 = hs[(wr + g + 8) * AST + kb + tt];
        unsigned a2 = hs[(wr + g) * AST + kb + tt + 4];
        unsigned a3 = hs[(wr + g + 8) * AST + kb + tt + 4];
#pragma unroll
        for (int nt = 0; nt < 16; nt++) {
            int n = nt * 8 + g;
            uint2 b01 = WtP[n * 32 + (((ks * 4 + tt) + 4 * (n & 3)) & 31)];
            asm volatile(
                "mma.sync.aligned.m16n8k16.row.col.f32.bf16.bf16.f32 "
                "{%0,%1,%2,%3}, {%4,%5,%6,%7}, {%8,%9}, {%0,%1,%2,%3};"
                : "+f"(c[nt][0]), "+f"(c[nt][1]), "+f"(c[nt][2]), "+f"(c[nt][3])
                : "r"(a0), "r"(a1), "r"(a2), "r"(a3), "r"(b01.x), "r"(b01.y));
        }
    }

    // epilogue: scale by dinv, pack bf16 pairs into g_mb
    int r0 = row0 + wr + g, r1 = r0 + 8;
    float d0 = g_dinv[r0], d1 = g_dinv[r1];
    unsigned* mb = (unsigned*)g_mb;
#pragma unroll
    for (int nt = 0; nt < 16; nt++) {
        int colp = nt * 4 + tt;
        __nv_bfloat162 p0 = __floats2bfloat162_rn(c[nt][0] * d0, c[nt][1] * d0);
        __nv_bfloat162 p1 = __floats2bfloat162_rn(c[nt][2] * d1, c[nt][3] * d1);
        mb[(size_t)r0 * 64 + colp] = *(unsigned*)&p0;
        mb[(size_t)r1 * 64 + colp] = *(unsigned*)&p1;
    }
}

// ---------------- aggregation: warp per node, bf16 gathers, 8-wide MLP ---------
__device__ __forceinline__ void acc_u2(float4& a, uint2 u) {
    float2 f0 = __bfloat1622float2(*(__nv_bfloat162*)&u.x);
    float2 f1 = __bfloat1622float2(*(__nv_bfloat162*)&u.y);
    a.x += f0.x; a.y += f0.y; a.z += f1.x; a.w += f1.y;
}

__global__ void k_agg(const float* __restrict__ bias, int last) {
    unsigned n = (blockIdx.x * blockDim.x + threadIdx.x) >> 5;
    if (n >= NN) return;
    int lane = threadIdx.x & 31;
    const uint2* mb = g_mb;
    float4 a0 = make_float4(0.f, 0.f, 0.f, 0.f);
    float4 a1 = a0, a2 = a0, a3 = a0;
    acc_u2(a0, __ldg(mb + (size_t)n * 32 + lane));    // self-loop term
    int s = g_off[n], e = g_off[n + 1];
    int i = s;
    for (; i + 8 <= e; i += 8) {
        int r0 = __ldg(g_csr + i),     r1 = __ldg(g_csr + i + 1);
        int r2 = __ldg(g_csr + i + 2), r3 = __ldg(g_csr + i + 3);
        int r4 = __ldg(g_csr + i + 4), r5 = __ldg(g_csr + i + 5);
        int r6 = __ldg(g_csr + i + 6), r7 = __ldg(g_csr + i + 7);
        uint2 v0 = __ldg(mb + (size_t)r0 * 32 + lane);
        uint2 v1 = __ldg(mb + (size_t)r1 * 32 + lane);
        uint2 v2 = __ldg(mb + (size_t)r2 * 32 + lane);
        uint2 v3 = __ldg(mb + (size_t)r3 * 32 + lane);
        uint2 v4 = __ldg(mb + (size_t)r4 * 32 + lane);
        uint2 v5 = __ldg(mb + (size_t)r5 * 32 + lane);
        uint2 v6 = __ldg(mb + (size_t)r6 * 32 + lane);
        uint2 v7 = __ldg(mb + (size_t)r7 * 32 + lane);
        acc_u2(a0, v0); acc_u2(a1, v1); acc_u2(a2, v2); acc_u2(a3, v3);
        acc_u2(a0, v4); acc_u2(a1, v5); acc_u2(a2, v6); acc_u2(a3, v7);
    }
    for (; i < e; i++) {
        int r = __ldg(g_csr + i);
        acc_u2(a0, __ldg(mb + (size_t)r * 32 + lane));
    }
    float sx = (a0.x + a1.x) + (a2.x + a3.x);
    float sy = (a0.y + a1.y) + (a2.y + a3.y);
    float sz = (a0.z + a1.z) + (a2.z + a3.z);
    float sw = (a0.w + a1.w) + (a2.w + a3.w);
    float d = g_dinv[n];
    float4 b = __ldg(((const float4*)bias) + lane);
    float ox = fmaxf(fmaf(d, sx, b.x), 0.f);
    float oy = fmaxf(fmaf(d, sy, b.y), 0.f);
    float oz = fmaxf(fmaf(d, sz, b.z), 0.f);
    float ow = fmaxf(fmaf(d, sw, b.w), 0.f);
    if (!last) {
        __nv_bfloat162 p0 = __floats2bfloat162_rn(ox, oy);
        __nv_bfloat162 p1 = __floats2bfloat162_rn(oz, ow);
        uint2 o; o.x = *(unsigned*)&p0; o.y = *(unsigned*)&p1;
        ((uint2*)g_hb)[(size_t)n * 32 + lane] = o;
    } else {
        float* dst = g_pool + g_batch[n] * H + lane * 4;
        asm volatile("red.global.add.v4.f32 [%0], {%1,%2,%3,%4};"
                     :: "l"(dst), "f"(ox), "f"(oy), "f"(oz), "f"(ow) : "memory");
    }
}

// ---------------- classifier + re-zero tail (replaces k_init) ----------------
__global__ void k_classifier(const float* __restrict__ Wc1, const float* __restrict__ bc1,
                             const float* __restrict__ Wc2, const float* __restrict__ bc2,
                             float* __restrict__ out) {
    __shared__ float gs[128];
    __shared__ float zs[64];
    int b = blockIdx.x, t = threadIdx.x;
    float cnt = fmaxf((float)g_cnt[b], 1.f);
    gs[t] = g_pool[b * H + t] / cnt;
    __syncthreads();
    if (t < 64) {
        float z = bc1[t];
#pragma unroll 4
        for (int k = 0; k < 128; k++) z = fmaf(gs[k], Wc1[k * 64 + t], z);
        z = fmaxf(z, 0.f);
        zs[t] = z * Wc2[t];
    }
    __syncthreads();
    if (t == 0) {
        float s = bc2[0];
#pragma unroll
        for (int k = 0; k < 64; k++) s += zs[k];
        out[b] = 1.f / (1.f + expf(-s));
    }
    // restore the zero-invariant for the next replay (each block touches only
    // regions it has finished reading)
    g_pool[b * H + t] = 0.f;
    if (t == 0) g_cnt[b] = 0;
    for (int i = b * 128 + t; i < NN; i += NG * 128) g_deg[i] = 0;
}

// ---------------- launch ----------------
extern "C" void kernel_launch(void* const* d_in, const int* in_sizes, int n_in,
                              void* d_out, int out_size) {
    const float* x     = (const float*)d_in[0];
    const void*  ei    = d_in[1];
    const void*  batch = d_in[2];
    const float* W_emb = (const float*)d_in[3];
    const float* b_emb = (const float*)d_in[4];
    const float* W_gnn = (const float*)d_in[5];
    const float* b_gnn = (const float*)d_in[6];
    const float* W_c1  = (const float*)d_in[7];
    const float* b_c1  = (const float*)d_in[8];
    const float* W_c2  = (const float*)d_in[9];
    const float* b_c2  = (const float*)d_in[10];
    float* out = (float*)d_out;

    const int GEMM_SMEM = (128 * AST + 128 * 64) * 4;   // 67584 B
    cudaFuncSetAttribute(k_gemm, cudaFuncAttributeMaxDynamicSharedMemorySize, GEMM_SMEM);
    const int NSCAN = (NN + 1023) / 1024;

    k_conv_edges<<<NE / 256, 256>>>(ei);                 // 0
    k_scan1<<<NSCAN, 1024>>>();                          // 1
    k_scan3<<<NSCAN, 1024>>>();                          // 2
    k_scatter<<<NE / 256, 256>>>();                      // 3  <- ncu window
    k_conv_batch<<<(NN + 255) / 256, 256>>>(batch, ei);  // 4
    k_uv<<<1, 128>>>(W_emb, b_emb, W_gnn);               // 5

    // layer 0 (rank-1 collapse)
    k_m0<<<NN * 32 / 256, 256>>>(x);
    k_agg<<<NN * 32 / 256, 256>>>(b_gnn, 0);

    // layers 1..2
    for (int l = 1; l < 3; l++) {
        k_gemm<<<NN_PAD / 128, 256, GEMM_SMEM>>>(W_gnn + (size_t)l * H * H);
        k_agg<<<NN * 32 / 256, 256>>>(b_gnn + l * H, l == 2);
    }

    k_classifier<<<NG, 128>>>(W_c1, b_c1, W_c2, b_c2, out);
}